// round 1
// baseline (speedup 1.0000x reference)
#include <cuda_runtime.h>
#include <cstdint>
#include <cstddef>

#define BB    8
#define NPER  4096
#define MDOWN 1024
#define KNN   32
#define CIN   64
#define DIN   67      // CIN + 3
#define COUT  128
#define EPSV  1e-5f

#define INFF __int_as_float(0x7f800000)

// scratch: knn indices per (batch, downsampled point)
__device__ int g_knn[BB * MDOWN * KNN];

// ---------------------------------------------------------------------------
// Kernel 1: kNN. One block per downsampled point (B*M = 8192 blocks, 128 thr).
// Computes d2 to all 4096 batch points into smem, then 32 tournament rounds of
// lexicographic argmin (d, idx) with lazy per-thread local-min recompute.
// ---------------------------------------------------------------------------
__global__ __launch_bounds__(128) void knn_kernel(const float* __restrict__ pos)
{
    __shared__ float dist[NPER];                 // 16 KB
    __shared__ unsigned long long wmin[4];
    __shared__ int sel[KNN];

    int blk = blockIdx.x;
    int b = blk / MDOWN;
    int i = blk - b * MDOWN;
    int t = threadIdx.x;
    const float* pbase = pos + (size_t)b * NPER * 3;

    float qx = pbase[i * 3 + 0];
    float qy = pbase[i * 3 + 1];
    float qz = pbase[i * 3 + 2];

    #pragma unroll
    for (int s = 0; s < NPER / 128; s++) {
        int p = t + s * 128;
        float dx = pbase[p * 3 + 0] - qx;
        float dy = pbase[p * 3 + 1] - qy;
        float dz = pbase[p * 3 + 2] - qz;
        dist[p] = dx * dx + dy * dy + dz * dz;
    }
    __syncthreads();

    // local min over strided region (p = t + 128*s, ascending -> lowest idx on tie)
    float bd = INFF; int bp = NPER;
    #pragma unroll
    for (int s = 0; s < NPER / 128; s++) {
        int p = t + s * 128;
        float d = dist[p];
        if (d < bd) { bd = d; bp = p; }
    }
    unsigned long long key =
        ((unsigned long long)__float_as_uint(bd) << 32) | (unsigned)bp;

    int lane = t & 31, warp = t >> 5;

    for (int r = 0; r < KNN; r++) {
        unsigned long long k = key;
        #pragma unroll
        for (int off = 16; off; off >>= 1) {
            unsigned long long o = __shfl_xor_sync(0xffffffffu, k, off);
            if (o < k) k = o;
        }
        if (lane == 0) wmin[warp] = k;
        __syncthreads();
        unsigned long long w = wmin[0];
        if (wmin[1] < w) w = wmin[1];
        if (wmin[2] < w) w = wmin[2];
        if (wmin[3] < w) w = wmin[3];
        int widx = (int)(w & 0xffffffffull);
        if (t == 0) sel[r] = widx;
        // owner of widx removes it and recomputes its local min
        if ((widx & 127) == t) {
            dist[widx] = INFF;
            bd = INFF; bp = NPER;
            #pragma unroll
            for (int s = 0; s < NPER / 128; s++) {
                int p = t + s * 128;
                float d = dist[p];
                if (d < bd) { bd = d; bp = p; }
            }
            key = ((unsigned long long)__float_as_uint(bd) << 32) | (unsigned)bp;
        }
        __syncthreads();
    }

    if (t < KNN) g_knn[blk * KNN + t] = sel[t];
}

// ---------------------------------------------------------------------------
// Kernel 2: gather + MLP (Linear->LN->GELU x2) + max-pool over K.
// 2 downsampled points per 256-thread block; weights/biases staged in SMEM.
// Warp w: point pt = w/4, rows k = (w%4)*8 .. +7. Lane owns channels 4*lane+q.
// ---------------------------------------------------------------------------
__device__ __forceinline__ float gelu_exact(float v)
{
    return 0.5f * v * (1.0f + erff(v * 0.7071067811865476f));
}

// dynamic smem layout (floats):
//   sW1 [67*128]        = 8576
//   sW2 [128*128]       = 16384
//   sB  [6*128]         = 768     (b1,g1,be1,b2,g2,be2)
//   sH  [2][32][68]     = 4352
//   sH1 [8][8][128]     = 8192
//   sMx [2][4][128]     = 1024
//   sIdx[2*32] ints     = 64
#define MLP_SMEM_FLOATS (8576 + 16384 + 768 + 4352 + 8192 + 1024)
#define MLP_SMEM_BYTES  (MLP_SMEM_FLOATS * 4 + 2 * KNN * 4)

__global__ __launch_bounds__(256) void mlp_kernel(
    const float* __restrict__ x, const float* __restrict__ pos,
    const float* __restrict__ W1, const float* __restrict__ b1,
    const float* __restrict__ g1, const float* __restrict__ be1,
    const float* __restrict__ W2, const float* __restrict__ b2,
    const float* __restrict__ g2, const float* __restrict__ be2,
    float* __restrict__ xd)
{
    extern __shared__ float sm[];
    float* sW1 = sm;
    float* sW2 = sW1 + DIN * COUT;
    float* sB  = sW2 + COUT * COUT;
    float* sH  = sB + 6 * COUT;
    float* sH1 = sH + 2 * KNN * 68;
    float* sMx = sH1 + 8 * 8 * COUT;
    int*   sIdx = (int*)(sMx + 2 * 4 * COUT);

    int t = threadIdx.x;

    // stage weights
    for (int u = t; u < DIN * COUT / 4; u += 256)
        ((float4*)sW1)[u] = ((const float4*)W1)[u];
    for (int u = t; u < COUT * COUT / 4; u += 256)
        ((float4*)sW2)[u] = ((const float4*)W2)[u];
    if (t < COUT) {
        sB[t]            = b1[t];
        sB[COUT + t]     = g1[t];
        sB[2 * COUT + t] = be1[t];
        sB[3 * COUT + t] = b2[t];
        sB[4 * COUT + t] = g2[t];
        sB[5 * COUT + t] = be2[t];
    }
    int g0 = blockIdx.x * 2;
    if (t < 2 * KNN) sIdx[t] = g_knn[g0 * KNN + t];
    __syncthreads();

    int warp = t >> 5, lane = t & 31;

    // gather h = [knn_feat | rel_pos] : warp handles 8 of the 64 combined rows
    #pragma unroll
    for (int rr = 0; rr < 8; rr++) {
        int row = warp * 8 + rr;         // 0..63
        int ptg = row >> 5;              // 0/1
        int k   = row & 31;
        int gpt = g0 + ptg;
        int b  = gpt >> 10;
        int ii = gpt & (MDOWN - 1);
        int idx = sIdx[ptg * KNN + k];
        const float* xr = x + ((size_t)(b * NPER + idx)) * CIN;
        float* hr = sH + (ptg * KNN + k) * 68;
        hr[lane]      = xr[lane];
        hr[lane + 32] = xr[lane + 32];
        if (lane < 3) {
            hr[64 + lane] = pos[((size_t)(b * NPER + idx)) * 3 + lane]
                          - pos[((size_t)(b * NPER + ii)) * 3 + lane];
        }
    }
    __syncthreads();

    int pt = warp >> 2;
    int wl = warp & 3;
    int gpt = g0 + pt;
    const float* hbase = sH + (pt * KNN + wl * 8) * 68;
    float* h1base = sH1 + warp * 8 * COUT;
    int c0 = lane * 4;

    // ---- layer 1: y = h @ W1 + b1 ----
    float acc[8][4];
    #pragma unroll
    for (int r = 0; r < 8; r++) {
        #pragma unroll
        for (int q = 0; q < 4; q++) acc[r][q] = sB[c0 + q];
    }
    for (int j = 0; j < DIN; j++) {
        float4 w = *(const float4*)(sW1 + j * COUT + c0);
        #pragma unroll
        for (int r = 0; r < 8; r++) {
            float hj = hbase[r * 68 + j];
            acc[r][0] = fmaf(hj, w.x, acc[r][0]);
            acc[r][1] = fmaf(hj, w.y, acc[r][1]);
            acc[r][2] = fmaf(hj, w.z, acc[r][2]);
            acc[r][3] = fmaf(hj, w.w, acc[r][3]);
        }
    }
    // LN1 + GELU -> smem h1
    #pragma unroll
    for (int r = 0; r < 8; r++) {
        float s = acc[r][0] + acc[r][1] + acc[r][2] + acc[r][3];
        #pragma unroll
        for (int off = 16; off; off >>= 1) s += __shfl_xor_sync(~0u, s, off);
        float mu = s * (1.0f / COUT);
        float d0 = acc[r][0] - mu, d1 = acc[r][1] - mu;
        float d2 = acc[r][2] - mu, d3 = acc[r][3] - mu;
        float ss = d0 * d0 + d1 * d1 + d2 * d2 + d3 * d3;
        #pragma unroll
        for (int off = 16; off; off >>= 1) ss += __shfl_xor_sync(~0u, ss, off);
        float inv = rsqrtf(ss * (1.0f / COUT) + EPSV);
        float4 o;
        o.x = gelu_exact(d0 * inv * sB[COUT + c0 + 0] + sB[2 * COUT + c0 + 0]);
        o.y = gelu_exact(d1 * inv * sB[COUT + c0 + 1] + sB[2 * COUT + c0 + 1]);
        o.z = gelu_exact(d2 * inv * sB[COUT + c0 + 2] + sB[2 * COUT + c0 + 2]);
        o.w = gelu_exact(d3 * inv * sB[COUT + c0 + 3] + sB[2 * COUT + c0 + 3]);
        *(float4*)(h1base + r * COUT + c0) = o;
    }
    __syncwarp();

    // ---- layer 2: y = h1 @ W2 + b2 ----
    float acc2[8][4];
    #pragma unroll
    for (int r = 0; r < 8; r++) {
        #pragma unroll
        for (int q = 0; q < 4; q++) acc2[r][q] = sB[3 * COUT + c0 + q];
    }
    for (int j = 0; j < COUT; j++) {
        float4 w = *(const float4*)(sW2 + j * COUT + c0);
        #pragma unroll
        for (int r = 0; r < 8; r++) {
            float hj = h1base[r * COUT + j];
            acc2[r][0] = fmaf(hj, w.x, acc2[r][0]);
            acc2[r][1] = fmaf(hj, w.y, acc2[r][1]);
            acc2[r][2] = fmaf(hj, w.z, acc2[r][2]);
            acc2[r][3] = fmaf(hj, w.w, acc2[r][3]);
        }
    }
    // LN2 + GELU + running max over the warp's 8 rows
    float mx0 = -INFF, mx1 = -INFF, mx2 = -INFF, mx3 = -INFF;
    #pragma unroll
    for (int r = 0; r < 8; r++) {
        float s = acc2[r][0] + acc2[r][1] + acc2[r][2] + acc2[r][3];
        #pragma unroll
        for (int off = 16; off; off >>= 1) s += __shfl_xor_sync(~0u, s, off);
        float mu = s * (1.0f / COUT);
        float d0 = acc2[r][0] - mu, d1 = acc2[r][1] - mu;
        float d2 = acc2[r][2] - mu, d3 = acc2[r][3] - mu;
        float ss = d0 * d0 + d1 * d1 + d2 * d2 + d3 * d3;
        #pragma unroll
        for (int off = 16; off; off >>= 1) ss += __shfl_xor_sync(~0u, ss, off);
        float inv = rsqrtf(ss * (1.0f / COUT) + EPSV);
        float v0 = gelu_exact(d0 * inv * sB[4 * COUT + c0 + 0] + sB[5 * COUT + c0 + 0]);
        float v1 = gelu_exact(d1 * inv * sB[4 * COUT + c0 + 1] + sB[5 * COUT + c0 + 1]);
        float v2 = gelu_exact(d2 * inv * sB[4 * COUT + c0 + 2] + sB[5 * COUT + c0 + 2]);
        float v3 = gelu_exact(d3 * inv * sB[4 * COUT + c0 + 3] + sB[5 * COUT + c0 + 3]);
        mx0 = fmaxf(mx0, v0); mx1 = fmaxf(mx1, v1);
        mx2 = fmaxf(mx2, v2); mx3 = fmaxf(mx3, v3);
    }
    {
        float4 m; m.x = mx0; m.y = mx1; m.z = mx2; m.w = mx3;
        *(float4*)(sMx + (pt * 4 + wl) * COUT + c0) = m;
    }
    __syncthreads();

    // cross-warp max (4 warps per point) and store
    if (wl == 0) {
        const float* m0 = sMx + pt * 4 * COUT;
        float4 a = *(const float4*)(m0 + 0 * COUT + c0);
        float4 b4 = *(const float4*)(m0 + 1 * COUT + c0);
        float4 c4 = *(const float4*)(m0 + 2 * COUT + c0);
        float4 d4 = *(const float4*)(m0 + 3 * COUT + c0);
        float4 o;
        o.x = fmaxf(fmaxf(a.x, b4.x), fmaxf(c4.x, d4.x));
        o.y = fmaxf(fmaxf(a.y, b4.y), fmaxf(c4.y, d4.y));
        o.z = fmaxf(fmaxf(a.z, b4.z), fmaxf(c4.z, d4.z));
        o.w = fmaxf(fmaxf(a.w, b4.w), fmaxf(c4.w, d4.w));
        *(float4*)(xd + (size_t)gpt * COUT + c0) = o;
    }
}

// ---------------------------------------------------------------------------
// Kernel 3: upsample nearest-neighbor index. grid (16, 8), 256 threads.
// ---------------------------------------------------------------------------
__global__ __launch_bounds__(256) void upsample_kernel(
    const float* __restrict__ pos, float* __restrict__ outF,
    long long* __restrict__ outI, int mode)
{
    __shared__ float pd[MDOWN * 3];   // 12 KB
    int b = blockIdx.y;
    const float* pbase = pos + (size_t)b * NPER * 3;
    for (int u = threadIdx.x; u < MDOWN * 3; u += 256) pd[u] = pbase[u];
    __syncthreads();

    int p = blockIdx.x * 256 + threadIdx.x;  // 0..4095
    float qx = pbase[p * 3 + 0];
    float qy = pbase[p * 3 + 1];
    float qz = pbase[p * 3 + 2];
    float bd = INFF; int bi = 0;
    for (int j = 0; j < MDOWN; j++) {
        float dx = qx - pd[j * 3 + 0];
        float dy = qy - pd[j * 3 + 1];
        float dz = qz - pd[j * 3 + 2];
        float d = dx * dx + dy * dy + dz * dz;
        if (d < bd) { bd = d; bi = j; }
    }
    long long res = (long long)bi + (long long)b * MDOWN;
    int gidx = b * NPER + p;
    if (mode) outI[gidx] = res;
    else      outF[gidx] = (float)res;
}

// ---------------------------------------------------------------------------
// Kernel 4: pos_down_flat + batch_down outputs.
// ---------------------------------------------------------------------------
__global__ __launch_bounds__(256) void misc_kernel(
    const float* __restrict__ pos, float* __restrict__ outBase, int mode)
{
    int t = blockIdx.x * 256 + threadIdx.x;
    if (t >= BB * MDOWN) return;
    int b = t >> 10;
    int i = t & (MDOWN - 1);
    const float* src = pos + ((size_t)b * NPER + i) * 3;
    float* pdst = outBase + (size_t)BB * MDOWN * COUT + (size_t)t * 3;
    pdst[0] = src[0]; pdst[1] = src[1]; pdst[2] = src[2];
    if (mode) {
        long long* bd = (long long*)((char*)outBase
            + (size_t)(BB * MDOWN * COUT + BB * MDOWN * 3) * 4);
        bd[t] = (long long)b;
    } else {
        outBase[(size_t)BB * MDOWN * COUT + BB * MDOWN * 3 + t] = (float)b;
    }
}

// ---------------------------------------------------------------------------
// launcher
// ---------------------------------------------------------------------------
extern "C" void kernel_launch(void* const* d_in, const int* in_sizes, int n_in,
                              void* d_out, int out_size)
{
    const float* x   = (const float*)d_in[0];
    const float* pos = (const float*)d_in[1];
    // d_in[2] = batch (int64, unused — layout is fixed)
    const float* W1  = (const float*)d_in[3];
    const float* b1  = (const float*)d_in[4];
    const float* g1  = (const float*)d_in[5];
    const float* be1 = (const float*)d_in[6];
    const float* W2  = (const float*)d_in[7];
    const float* b2  = (const float*)d_in[8];
    const float* g2  = (const float*)d_in[9];
    const float* be2 = (const float*)d_in[10];
    float* out = (float*)d_out;

    // Output tuple packing convention (branch on out_size):
    //   float-concat: xd[1048576] | pd[24576] | batch_down[8192] | up_idx[32768]
    //   int64 tail:   same, but batch_down/up_idx stored as int64
    //   xd-only:      just x_down
    const int FLOAT_FULL = BB * MDOWN * COUT + BB * MDOWN * 3 + BB * MDOWN + BB * NPER;          // 1114112
    const int I64_FULL   = BB * MDOWN * COUT + BB * MDOWN * 3 + 2 * (BB * MDOWN + BB * NPER);    // 1155072
    int mode;  // 0 = float full, 1 = int64 full, 2 = xd only
    if (out_size == I64_FULL)          mode = 1;
    else if (out_size >= FLOAT_FULL)   mode = 0;
    else                               mode = 2;

    cudaFuncSetAttribute(mlp_kernel,
        cudaFuncAttributeMaxDynamicSharedMemorySize, MLP_SMEM_BYTES);

    knn_kernel<<<BB * MDOWN, 128>>>(pos);

    mlp_kernel<<<BB * MDOWN / 2, 256, MLP_SMEM_BYTES>>>(
        x, pos, W1, b1, g1, be1, W2, b2, g2, be2, out);

    if (mode != 2) {
        long long* outUI = (long long*)((char*)d_out
            + (size_t)(BB * MDOWN * COUT + BB * MDOWN * 3) * 4
            + (size_t)(BB * MDOWN) * 8);
        float* outUF = out + (size_t)(BB * MDOWN * COUT + BB * MDOWN * 3 + BB * MDOWN);
        dim3 ug(NPER / 256, BB);
        upsample_kernel<<<ug, 256>>>(pos, outUF, outUI, mode);
        misc_kernel<<<(BB * MDOWN + 255) / 256, 256>>>(pos, out, mode);
    }
}

// round 3
// speedup vs baseline: 1.6646x; 1.6646x over previous
#include <cuda_runtime.h>
#include <cuda_bf16.h>
#include <cstdint>
#include <cstddef>

#define BB    8
#define NPER  4096
#define MDOWN 1024
#define KNN   32
#define CIN   64
#define COUT  128
#define EPSV  1e-5f

#define INFF __int_as_float(0x7f800000)

__device__ int g_knn[BB * MDOWN * KNN];

// ---------------------------------------------------------------------------
// warp-mma helpers (sm_80+ features, valid on plain sm_103 target)
// ---------------------------------------------------------------------------
__device__ __forceinline__ uint32_t smem_u32(const void* p) {
    uint32_t a;
    asm("{ .reg .u64 t; cvta.to.shared.u64 t, %1; cvt.u32.u64 %0, t; }" : "=r"(a) : "l"(p));
    return a;
}

__device__ __forceinline__ void ldsm4(uint32_t* r, uint32_t addr) {
    asm volatile("ldmatrix.sync.aligned.m8n8.x4.shared.b16 {%0,%1,%2,%3}, [%4];"
        : "=r"(r[0]), "=r"(r[1]), "=r"(r[2]), "=r"(r[3]) : "r"(addr));
}

__device__ __forceinline__ void mma16816(float* d, const uint32_t* a, const uint32_t* b) {
    asm volatile(
        "mma.sync.aligned.m16n8k16.row.col.f32.bf16.bf16.f32 "
        "{%0,%1,%2,%3}, {%4,%5,%6,%7}, {%8,%9}, {%0,%1,%2,%3};"
        : "+f"(d[0]), "+f"(d[1]), "+f"(d[2]), "+f"(d[3])
        : "r"(a[0]), "r"(a[1]), "r"(a[2]), "r"(a[3]), "r"(b[0]), "r"(b[1]));
}

__device__ __forceinline__ void split_pair(float v0, float v1, uint32_t& p0, uint32_t& p1) {
    __nv_bfloat16 a0 = __float2bfloat16_rn(v0);
    __nv_bfloat16 b0 = __float2bfloat16_rn(v1);
    float r0 = v0 - __bfloat162float(a0);
    float r1 = v1 - __bfloat162float(b0);
    __nv_bfloat16 a1 = __float2bfloat16_rn(r0);
    __nv_bfloat16 b1 = __float2bfloat16_rn(r1);
    p0 = ((uint32_t)__bfloat16_as_ushort(b0) << 16) | (uint32_t)__bfloat16_as_ushort(a0);
    p1 = ((uint32_t)__bfloat16_as_ushort(b1) << 16) | (uint32_t)__bfloat16_as_ushort(a1);
}

__device__ __forceinline__ float gelu_exact(float v) {
    return 0.5f * v * (1.0f + erff(v * 0.7071067811865476f));
}

// NK k-steps of 16; full 128x128 tile per block, warp = 32x64 subtile
template<int NK>
__device__ __forceinline__ void gemm_tile(uint32_t a0Addr, uint32_t a1Addr,
                                          const uint32_t* bAddr, float (*d)[8][4]) {
    #pragma unroll
    for (int k = 0; k < NK; k++) {
        uint32_t a0[4], a1[4];
        ldsm4(a0, a0Addr + k * 32);
        ldsm4(a1, a1Addr + k * 32);
        #pragma unroll
        for (int jj = 0; jj < 4; jj++) {
            uint32_t bb[4];
            ldsm4(bb, bAddr[jj] + k * 32);
            mma16816(d[0][2 * jj],     a0, bb);
            mma16816(d[0][2 * jj + 1], a0, bb + 2);
            mma16816(d[1][2 * jj],     a1, bb);
            mma16816(d[1][2 * jj + 1], a1, bb + 2);
        }
    }
}

// ---------------------------------------------------------------------------
// Kernel 1: kNN (unchanged, validated)
// ---------------------------------------------------------------------------
__global__ __launch_bounds__(128) void knn_kernel(const float* __restrict__ pos)
{
    __shared__ float dist[NPER];
    __shared__ unsigned long long wmin[4];
    __shared__ int sel[KNN];

    int blk = blockIdx.x;
    int b = blk / MDOWN;
    int i = blk - b * MDOWN;
    int t = threadIdx.x;
    const float* pbase = pos + (size_t)b * NPER * 3;

    float qx = pbase[i * 3 + 0];
    float qy = pbase[i * 3 + 1];
    float qz = pbase[i * 3 + 2];

    #pragma unroll
    for (int s = 0; s < NPER / 128; s++) {
        int p = t + s * 128;
        float dx = pbase[p * 3 + 0] - qx;
        float dy = pbase[p * 3 + 1] - qy;
        float dz = pbase[p * 3 + 2] - qz;
        dist[p] = dx * dx + dy * dy + dz * dz;
    }
    __syncthreads();

    float bd = INFF; int bp = NPER;
    #pragma unroll
    for (int s = 0; s < NPER / 128; s++) {
        int p = t + s * 128;
        float d = dist[p];
        if (d < bd) { bd = d; bp = p; }
    }
    unsigned long long key =
        ((unsigned long long)__float_as_uint(bd) << 32) | (unsigned)bp;

    int lane = t & 31, warp = t >> 5;

    for (int r = 0; r < KNN; r++) {
        unsigned long long k = key;
        #pragma unroll
        for (int off = 16; off; off >>= 1) {
            unsigned long long o = __shfl_xor_sync(0xffffffffu, k, off);
            if (o < k) k = o;
        }
        if (lane == 0) wmin[warp] = k;
        __syncthreads();
        unsigned long long w = wmin[0];
        if (wmin[1] < w) w = wmin[1];
        if (wmin[2] < w) w = wmin[2];
        if (wmin[3] < w) w = wmin[3];
        int widx = (int)(w & 0xffffffffull);
        if (t == 0) sel[r] = widx;
        if ((widx & 127) == t) {
            dist[widx] = INFF;
            bd = INFF; bp = NPER;
            #pragma unroll
            for (int s = 0; s < NPER / 128; s++) {
                int p = t + s * 128;
                float d = dist[p];
                if (d < bd) { bd = d; bp = p; }
            }
            key = ((unsigned long long)__float_as_uint(bd) << 32) | (unsigned)bp;
        }
        __syncthreads();
    }

    if (t < KNN) g_knn[blk * KNN + t] = sel[t];
}

// ---------------------------------------------------------------------------
// Kernel 2: HMMA MLP. Block = 128 rows (4 points x 32 nbrs), 256 threads.
// ---------------------------------------------------------------------------
// smem byte offsets (dynamic)
#define OW_A 0
#define OW_B 34816
#define OA_A 69632
#define OA_B 104448
#define OPAR 139264
#define OIDX 141824
#define SM_TOTAL 142336

#define STR1 176   // layer1 row stride bytes (88 bf16) - ldsm conflict-free
#define STR2 272   // layer2 row stride bytes (136 bf16)
#define DSTR 132   // dump row stride in f32 words

__global__ __launch_bounds__(256)
void mlp_mma_kernel(
    const float* __restrict__ x, const float* __restrict__ pos,
    const float* __restrict__ W1, const float* __restrict__ b1,
    const float* __restrict__ g1, const float* __restrict__ be1,
    const float* __restrict__ W2, const float* __restrict__ b2,
    const float* __restrict__ g2, const float* __restrict__ be2,
    float* __restrict__ xd)
{
    extern __shared__ char smc[];
    uint32_t sbase = smem_u32(smc);
    float* dump = (float*)smc;               // aliases OW region after mma
    float* sP = (float*)(smc + OPAR);        // g1 be1 b2 g2 be2
    int* sIdx = (int*)(smc + OIDX);

    int t = threadIdx.x;
    int lane = t & 31, w = t >> 5;
    int mw = w & 3, nh = w >> 2;
    int g0 = blockIdx.x * 4;

    // ---- stage params + knn idx ----
    if (t < 128) {
        sP[t]       = g1[t];
        sP[128 + t] = be1[t];
        sP[256 + t] = b2[t];
        sP[384 + t] = g2[t];
        sP[512 + t] = be2[t];
        sIdx[t] = g_knn[blockIdx.x * 128 + t];
    }

    // ---- stage Wt1 (row n, cols k; k==67 -> b1; 68..79 zero) ----
    {
        int r = t >> 1, h = t & 1;
        #pragma unroll
        for (int kk = 0; kk < 40; kk += 2) {
            int k = h * 40 + kk;
            float v0 = (k < 67) ? W1[k * COUT + r] : ((k == 67) ? b1[r] : 0.0f);
            float v1 = (k + 1 < 67) ? W1[(k + 1) * COUT + r] : ((k + 1 == 67) ? b1[r] : 0.0f);
            uint32_t p0, p1;
            split_pair(v0, v1, p0, p1);
            *(uint32_t*)(smc + OW_A + r * STR1 + k * 2) = p0;
            *(uint32_t*)(smc + OW_B + r * STR1 + k * 2) = p1;
        }
    }

    // ---- gather A1 (thread t = row t) ----
    if (t < 128) {
        int p = t >> 5, kn = t & 31;
        int gpt = g0 + p;
        int b = gpt >> 10;
        int ii = gpt & (MDOWN - 1);
        int idx = sIdx[p * KNN + kn];
        const float4* xr = (const float4*)(x + ((size_t)(b * NPER + idx)) * CIN);
        char* rowA = smc + OA_A + t * STR1;
        char* rowB = smc + OA_B + t * STR1;
        #pragma unroll
        for (int q = 0; q < 16; q++) {
            float4 f = xr[q];
            uint32_t p0, p1;
            split_pair(f.x, f.y, p0, p1);
            *(uint32_t*)(rowA + q * 8)     = p0;
            *(uint32_t*)(rowB + q * 8)     = p1;
            split_pair(f.z, f.w, p0, p1);
            *(uint32_t*)(rowA + q * 8 + 4) = p0;
            *(uint32_t*)(rowB + q * 8 + 4) = p1;
        }
        const float* pn = pos + ((size_t)(b * NPER + idx)) * 3;
        const float* pc = pos + ((size_t)(b * NPER + ii)) * 3;
        uint32_t p0, p1;
        split_pair(pn[0] - pc[0], pn[1] - pc[1], p0, p1);
        *(uint32_t*)(rowA + 128) = p0;
        *(uint32_t*)(rowB + 128) = p1;
        split_pair(pn[2] - pc[2], 1.0f, p0, p1);   // col 67 = bias input
        *(uint32_t*)(rowA + 132) = p0;
        *(uint32_t*)(rowB + 132) = p1;
        #pragma unroll
        for (int kk = 68; kk < 80; kk += 2) {
            *(uint32_t*)(rowA + kk * 2) = 0u;
            *(uint32_t*)(rowB + kk * 2) = 0u;
        }
    }
    __syncthreads();

    int arow = mw * 32 + (lane & 15);
    int brow = nh * 64 + (lane & 7) + ((lane >> 4) << 3);
    int koff16 = ((lane >> 3) & 1) * 16;
    int acolg = (lane >> 4) * 16;

    // ================= layer 1: K=80 (5 k-steps) =================
    float d[2][8][4];
    #pragma unroll
    for (int i = 0; i < 2; i++)
        #pragma unroll
        for (int j = 0; j < 8; j++)
            #pragma unroll
            for (int q = 0; q < 4; q++) d[i][j][q] = 0.0f;

    {
        uint32_t aA = sbase + OA_A + arow * STR1 + acolg;
        uint32_t aB = sbase + OA_B + arow * STR1 + acolg;
        uint32_t wA = sbase + OW_A + brow * STR1 + koff16;
        uint32_t wB = sbase + OW_B + brow * STR1 + koff16;
        uint32_t bA[4], bB[4];
        #pragma unroll
        for (int jj = 0; jj < 4; jj++) { bA[jj] = wA + jj * 16 * STR1; bB[jj] = wB + jj * 16 * STR1; }
        gemm_tile<5>(aA, aA + 16 * STR1, bA, d);
        gemm_tile<5>(aB, aB + 16 * STR1, bA, d);
        gemm_tile<5>(aA, aA + 16 * STR1, bB, d);
    }
    __syncthreads();

    // dump D1 -> f32 smem
    {
        int g = lane >> 2, tq = lane & 3;
        #pragma unroll
        for (int i = 0; i < 2; i++) {
            int r0 = mw * 32 + i * 16 + g;
            #pragma unroll
            for (int j = 0; j < 8; j++) {
                int c = nh * 64 + j * 8 + 2 * tq;
                *(float2*)&dump[r0 * DSTR + c]       = make_float2(d[i][j][0], d[i][j][1]);
                *(float2*)&dump[(r0 + 8) * DSTR + c] = make_float2(d[i][j][2], d[i][j][3]);
            }
        }
    }
    __syncthreads();

    // epilogue 1: LN + GELU -> bf16 splits into OA regions (stride STR2)
    {
        int r = t >> 1, h = t & 1;
        const float4* row = (const float4*)(dump + r * DSTR + h * 64);
        float s = 0.0f, ss = 0.0f;
        #pragma unroll
        for (int q = 0; q < 16; q++) {
            float4 f = row[q];
            s += f.x + f.y + f.z + f.w;
            ss = fmaf(f.x, f.x, fmaf(f.y, f.y, fmaf(f.z, f.z, fmaf(f.w, f.w, ss))));
        }
        s  += __shfl_xor_sync(0xffffffffu, s, 1);
        ss += __shfl_xor_sync(0xffffffffu, ss, 1);
        float mu = s * (1.0f / COUT);
        float inv = rsqrtf(ss * (1.0f / COUT) - mu * mu + EPSV);
        char* rowA = smc + OA_A + r * STR2;
        char* rowB = smc + OA_B + r * STR2;
        #pragma unroll
        for (int q = 0; q < 16; q++) {
            float4 f = row[q];
            int c = h * 64 + q * 4;
            float v0 = gelu_exact((f.x - mu) * inv * sP[c]     + sP[128 + c]);
            float v1 = gelu_exact((f.y - mu) * inv * sP[c + 1] + sP[128 + c + 1]);
            float v2 = gelu_exact((f.z - mu) * inv * sP[c + 2] + sP[128 + c + 2]);
            float v3 = gelu_exact((f.w - mu) * inv * sP[c + 3] + sP[128 + c + 3]);
            uint32_t p0, p1;
            split_pair(v0, v1, p0, p1);
            *(uint32_t*)(rowA + c * 2)     = p0;
            *(uint32_t*)(rowB + c * 2)     = p1;
            split_pair(v2, v3, p0, p1);
            *(uint32_t*)(rowA + c * 2 + 4) = p0;
            *(uint32_t*)(rowB + c * 2 + 4) = p1;
        }
    }
    __syncthreads();

    // stage Wt2 (overwrites dump/OW region)
    {
        int r = t >> 1, h = t & 1;
        #pragma unroll
        for (int kk = 0; kk < 64; kk += 2) {
            int k = h * 64 + kk;
            float v0 = W2[k * COUT + r];
            float v1 = W2[(k + 1) * COUT + r];
            uint32_t p0, p1;
            split_pair(v0, v1, p0, p1);
            *(uint32_t*)(smc + OW_A + r * STR2 + k * 2) = p0;
            *(uint32_t*)(smc + OW_B + r * STR2 + k * 2) = p1;
        }
    }
    __syncthreads();

    // ================= layer 2: K=128 (8 k-steps) =================
    #pragma unroll
    for (int i = 0; i < 2; i++)
        #pragma unroll
        for (int j = 0; j < 8; j++)
            #pragma unroll
            for (int q = 0; q < 4; q++) d[i][j][q] = 0.0f;

    {
        uint32_t aA = sbase + OA_A + arow * STR2 + acolg;
        uint32_t aB = sbase + OA_B + arow * STR2 + acolg;
        uint32_t wA = sbase + OW_A + brow * STR2 + koff16;
        uint32_t wB = sbase + OW_B + brow * STR2 + koff16;
        uint32_t bA[4], bB[4];
        #pragma unroll
        for (int jj = 0; jj < 4; jj++) { bA[jj] = wA + jj * 16 * STR2; bB[jj] = wB + jj * 16 * STR2; }
        gemm_tile<8>(aA, aA + 16 * STR2, bA, d);
        gemm_tile<8>(aB, aB + 16 * STR2, bA, d);
        gemm_tile<8>(aA, aA + 16 * STR2, bB, d);
    }
    __syncthreads();

    // dump D2
    {
        int g = lane >> 2, tq = lane & 3;
        #pragma unroll
        for (int i = 0; i < 2; i++) {
            int r0 = mw * 32 + i * 16 + g;
            #pragma unroll
            for (int j = 0; j < 8; j++) {
                int c = nh * 64 + j * 8 + 2 * tq;
                *(float2*)&dump[r0 * DSTR + c]       = make_float2(d[i][j][0], d[i][j][1]);
                *(float2*)&dump[(r0 + 8) * DSTR + c] = make_float2(d[i][j][2], d[i][j][3]);
            }
        }
    }
    __syncthreads();

    // epilogue 2: +b2, LN, GELU, write back f32 in-place
    {
        int r = t >> 1, h = t & 1;
        float* row = dump + r * DSTR + h * 64;
        float s = 0.0f, ss = 0.0f;
        #pragma unroll
        for (int q = 0; q < 16; q++) {
            float4 f = ((const float4*)row)[q];
            int c = h * 64 + q * 4;
            f.x += sP[256 + c]; f.y += sP[256 + c + 1];
            f.z += sP[256 + c + 2]; f.w += sP[256 + c + 3];
            s += f.x + f.y + f.z + f.w;
            ss = fmaf(f.x, f.x, fmaf(f.y, f.y, fmaf(f.z, f.z, fmaf(f.w, f.w, ss))));
        }
        s  += __shfl_xor_sync(0xffffffffu, s, 1);
        ss += __shfl_xor_sync(0xffffffffu, ss, 1);
        float mu = s * (1.0f / COUT);
        float inv = rsqrtf(ss * (1.0f / COUT) - mu * mu + EPSV);
        #pragma unroll
        for (int q = 0; q < 16; q++) {
            float4 f = ((const float4*)row)[q];
            int c = h * 64 + q * 4;
            f.x = gelu_exact((f.x + sP[256 + c]     - mu) * inv * sP[384 + c]     + sP[512 + c]);
            f.y = gelu_exact((f.y + sP[256 + c + 1] - mu) * inv * sP[384 + c + 1] + sP[512 + c + 1]);
            f.z = gelu_exact((f.z + sP[256 + c + 2] - mu) * inv * sP[384 + c + 2] + sP[512 + c + 2]);
            f.w = gelu_exact((f.w + sP[256 + c + 3] - mu) * inv * sP[384 + c + 3] + sP[512 + c + 3]);
            ((float4*)row)[q] = f;
        }
    }
    __syncthreads();

    // max-pool over 32 neighbors per point, store
    #pragma unroll
    for (int task = 0; task < 2; task++) {
        int id = t + task * 256;           // 0..511
        int p = id >> 7, c = id & 127;
        const float* col = dump + (p * 32) * DSTR + c;
        float m = -INFF;
        #pragma unroll
        for (int r2 = 0; r2 < 32; r2++)
            m = fmaxf(m, col[r2 * DSTR]);
        xd[(size_t)(g0 + p) * COUT + c] = m;
    }
}

// ---------------------------------------------------------------------------
// Kernel 3: upsample nearest index (unchanged)
// ---------------------------------------------------------------------------
__global__ __launch_bounds__(256) void upsample_kernel(
    const float* __restrict__ pos, float* __restrict__ outF,
    long long* __restrict__ outI, int mode)
{
    __shared__ float pd[MDOWN * 3];
    int b = blockIdx.y;
    const float* pbase = pos + (size_t)b * NPER * 3;
    for (int u = threadIdx.x; u < MDOWN * 3; u += 256) pd[u] = pbase[u];
    __syncthreads();

    int p = blockIdx.x * 256 + threadIdx.x;
    float qx = pbase[p * 3 + 0];
    float qy = pbase[p * 3 + 1];
    float qz = pbase[p * 3 + 2];
    float bd = INFF; int bi = 0;
    for (int j = 0; j < MDOWN; j++) {
        float dx = qx - pd[j * 3 + 0];
        float dy = qy - pd[j * 3 + 1];
        float dz = qz - pd[j * 3 + 2];
        float d = dx * dx + dy * dy + dz * dz;
        if (d < bd) { bd = d; bi = j; }
    }
    long long res = (long long)bi + (long long)b * MDOWN;
    int gidx = b * NPER + p;
    if (mode) outI[gidx] = res;
    else      outF[gidx] = (float)res;
}

// ---------------------------------------------------------------------------
// Kernel 4: pos_down / batch_down (unchanged)
// ---------------------------------------------------------------------------
__global__ __launch_bounds__(256) void misc_kernel(
    const float* __restrict__ pos, float* __restrict__ outBase, int mode)
{
    int t = blockIdx.x * 256 + threadIdx.x;
    if (t >= BB * MDOWN) return;
    int b = t >> 10;
    int i = t & (MDOWN - 1);
    const float* src = pos + ((size_t)b * NPER + i) * 3;
    float* pdst = outBase + (size_t)BB * MDOWN * COUT + (size_t)t * 3;
    pdst[0] = src[0]; pdst[1] = src[1]; pdst[2] = src[2];
    if (mode) {
        long long* bd = (long long*)((char*)outBase
            + (size_t)(BB * MDOWN * COUT + BB * MDOWN * 3) * 4);
        bd[t] = (long long)b;
    } else {
        outBase[(size_t)BB * MDOWN * COUT + BB * MDOWN * 3 + t] = (float)b;
    }
}

// ---------------------------------------------------------------------------
// launcher
// ---------------------------------------------------------------------------
extern "C" void kernel_launch(void* const* d_in, const int* in_sizes, int n_in,
                              void* d_out, int out_size)
{
    const float* x   = (const float*)d_in[0];
    const float* pos = (const float*)d_in[1];
    const float* W1  = (const float*)d_in[3];
    const float* b1  = (const float*)d_in[4];
    const float* g1  = (const float*)d_in[5];
    const float* be1 = (const float*)d_in[6];
    const float* W2  = (const float*)d_in[7];
    const float* b2  = (const float*)d_in[8];
    const float* g2  = (const float*)d_in[9];
    const float* be2 = (const float*)d_in[10];
    float* out = (float*)d_out;

    const int FLOAT_FULL = BB * MDOWN * COUT + BB * MDOWN * 3 + BB * MDOWN + BB * NPER;
    const int I64_FULL   = BB * MDOWN * COUT + BB * MDOWN * 3 + 2 * (BB * MDOWN + BB * NPER);
    int mode;
    if (out_size == I64_FULL)        mode = 1;
    else if (out_size >= FLOAT_FULL) mode = 0;
    else                             mode = 2;

    static int smem_set = 0;
    if (!smem_set) {
        cudaFuncSetAttribute(mlp_mma_kernel,
            cudaFuncAttributeMaxDynamicSharedMemorySize, SM_TOTAL);
        smem_set = 1;
    }

    knn_kernel<<<BB * MDOWN, 128>>>(pos);

    mlp_mma_kernel<<<BB * MDOWN / 4, 256, SM_TOTAL>>>(
        x, pos, W1, b1, g1, be1, W2, b2, g2, be2, out);

    if (mode != 2) {
        long long* outUI = (long long*)((char*)d_out
            + (size_t)(BB * MDOWN * COUT + BB * MDOWN * 3) * 4
            + (size_t)(BB * MDOWN) * 8);
        float* outUF = out + (size_t)(BB * MDOWN * COUT + BB * MDOWN * 3 + BB * MDOWN);
        dim3 ug(NPER / 256, BB);
        upsample_kernel<<<ug, 256>>>(pos, outUF, outUI, mode);
        misc_kernel<<<(BB * MDOWN + 255) / 256, 256>>>(pos, out, mode);
    }
}

// round 4
// speedup vs baseline: 2.5466x; 1.5299x over previous
#include <cuda_runtime.h>
#include <cuda_bf16.h>
#include <cstdint>
#include <cstddef>

#define BB    8
#define NPER  4096
#define MDOWN 1024
#define KNN   32
#define CIN   64
#define COUT  128
#define EPSV  1e-5f

#define INFF __int_as_float(0x7f800000)

__device__ int g_knn[BB * MDOWN * KNN];

// ---------------------------------------------------------------------------
// helpers
// ---------------------------------------------------------------------------
__device__ __forceinline__ uint32_t smem_u32(const void* p) {
    uint32_t a;
    asm("{ .reg .u64 t; cvta.to.shared.u64 t, %1; cvt.u32.u64 %0, t; }" : "=r"(a) : "l"(p));
    return a;
}

__device__ __forceinline__ void ldsm4(uint32_t* r, uint32_t addr) {
    asm volatile("ldmatrix.sync.aligned.m8n8.x4.shared.b16 {%0,%1,%2,%3}, [%4];"
        : "=r"(r[0]), "=r"(r[1]), "=r"(r[2]), "=r"(r[3]) : "r"(addr));
}

__device__ __forceinline__ void mma16816(float* d, const uint32_t* a, const uint32_t* b) {
    asm volatile(
        "mma.sync.aligned.m16n8k16.row.col.f32.bf16.bf16.f32 "
        "{%0,%1,%2,%3}, {%4,%5,%6,%7}, {%8,%9}, {%0,%1,%2,%3};"
        : "+f"(d[0]), "+f"(d[1]), "+f"(d[2]), "+f"(d[3])
        : "r"(a[0]), "r"(a[1]), "r"(a[2]), "r"(a[3]), "r"(b[0]), "r"(b[1]));
}

// fast 2-way bf16 split: p0 = bf16x2(v0,v1), p1 = bf16x2 of residuals
__device__ __forceinline__ void split2(float v0, float v1, uint32_t& p0, uint32_t& p1) {
    __nv_bfloat162 h0 = __floats2bfloat162_rn(v0, v1);
    uint32_t u = *reinterpret_cast<uint32_t*>(&h0);
    float f0 = __uint_as_float(u << 16);
    float f1 = __uint_as_float(u & 0xffff0000u);
    __nv_bfloat162 h1 = __floats2bfloat162_rn(v0 - f0, v1 - f1);
    p0 = u;
    p1 = *reinterpret_cast<uint32_t*>(&h1);
}

__device__ __forceinline__ float gelu_exact(float v) {
    return 0.5f * v * (1.0f + erff(v * 0.7071067811865476f));
}

template<int NK>
__device__ __forceinline__ void gemm_tile(uint32_t a0Addr, uint32_t a1Addr,
                                          const uint32_t* bAddr, float (*d)[8][4]) {
    #pragma unroll
    for (int k = 0; k < NK; k++) {
        uint32_t a0[4], a1[4];
        ldsm4(a0, a0Addr + k * 32);
        ldsm4(a1, a1Addr + k * 32);
        #pragma unroll
        for (int jj = 0; jj < 4; jj++) {
            uint32_t bb[4];
            ldsm4(bb, bAddr[jj] + k * 32);
            mma16816(d[0][2 * jj],     a0, bb);
            mma16816(d[0][2 * jj + 1], a0, bb + 2);
            mma16816(d[1][2 * jj],     a1, bb);
            mma16816(d[1][2 * jj + 1], a1, bb + 2);
        }
    }
}

// ---------------------------------------------------------------------------
// Kernel 1: kNN via histogram-select + bitonic sort. 1 block = 1 query.
// ---------------------------------------------------------------------------
__global__ __launch_bounds__(128) void knn_kernel(const float* __restrict__ pos)
{
    __shared__ float dist[NPER];                  // 16 KB
    __shared__ unsigned int hist[2048];           // 8 KB
    __shared__ unsigned long long cand[128];      // 1 KB
    __shared__ int ctrl[2];                       // nsel, B
    __shared__ unsigned int wtot[4];

    int blk = blockIdx.x;
    int b = blk >> 10;
    int i = blk & (MDOWN - 1);
    int t = threadIdx.x;
    int lane = t & 31, warp = t >> 5;
    const float* pbase = pos + (size_t)b * NPER * 3;

    #pragma unroll
    for (int s = 0; s < 16; s++) hist[t + s * 128] = 0u;
    if (t == 0) ctrl[0] = 0;

    float qx = pbase[i * 3 + 0];
    float qy = pbase[i * 3 + 1];
    float qz = pbase[i * 3 + 2];
    __syncthreads();

    // distances + histogram (bin = float bits >> 20, order preserving, d2>=0)
    #pragma unroll
    for (int s = 0; s < NPER / 128; s++) {
        int p = t + s * 128;
        float dx = pbase[p * 3 + 0] - qx;
        float dy = pbase[p * 3 + 1] - qy;
        float dz = pbase[p * 3 + 2] - qz;
        float d = dx * dx + dy * dy + dz * dz;
        dist[p] = d;
        atomicAdd(&hist[__float_as_uint(d) >> 20], 1u);
    }
    __syncthreads();

    // block scan over 2048 bins (16 per thread) to find boundary bin B
    unsigned int cnt = 0;
    #pragma unroll
    for (int k = 0; k < 16; k++) cnt += hist[t * 16 + k];
    unsigned int v = cnt;
    #pragma unroll
    for (int o = 1; o < 32; o <<= 1) {
        unsigned int u = __shfl_up_sync(0xffffffffu, v, o);
        if (lane >= o) v += u;
    }
    if (lane == 31) wtot[warp] = v;
    __syncthreads();
    unsigned int woff = 0;
    for (int w2 = 0; w2 < warp; w2++) woff += wtot[w2];
    unsigned int incl = v + woff;
    unsigned int excl = incl - cnt;
    if (excl < KNN && incl >= KNN) {
        unsigned int c = excl;
        #pragma unroll
        for (int k = 0; k < 16; k++) {
            unsigned int h = hist[t * 16 + k];
            if (c + h >= KNN) { ctrl[1] = t * 16 + k; break; }
            c += h;
        }
    }
    __syncthreads();
    int B = ctrl[1];

    // gather all keys with bin <= B
    #pragma unroll
    for (int s = 0; s < NPER / 128; s++) {
        int p = t + s * 128;
        unsigned int bits = __float_as_uint(dist[p]);
        if ((int)(bits >> 20) <= B) {
            int slot = atomicAdd(&ctrl[0], 1);
            if (slot < 128)
                cand[slot] = ((unsigned long long)bits << 32) | (unsigned)p;
        }
    }
    __syncthreads();
    int n = ctrl[0]; if (n > 128) n = 128;
    if (t >= n) cand[t] = ~0ull;
    __syncthreads();

    // bitonic sort of 128 u64 keys (ascending)
    for (int k = 2; k <= 128; k <<= 1) {
        for (int j = k >> 1; j > 0; j >>= 1) {
            int ixj = t ^ j;
            unsigned long long a = cand[t];
            unsigned long long c2 = cand[ixj];
            unsigned long long mn = (a < c2) ? a : c2;
            unsigned long long mx = (a < c2) ? c2 : a;
            bool up = ((t & k) == 0);
            unsigned long long res = (t < ixj) ? (up ? mn : mx) : (up ? mx : mn);
            __syncthreads();
            cand[t] = res;
            __syncthreads();
        }
    }
    if (t < KNN) g_knn[blk * KNN + t] = (int)(cand[t] & 0xffffffffu);
}

// ---------------------------------------------------------------------------
// Kernel 2: persistent HMMA MLP, fragment-space epilogues.
// Grid = 152 blocks x 256 threads; each block loops over tiles of 128 rows.
// ---------------------------------------------------------------------------
#define STR1 176
#define STR2 272

#define OW1A 0
#define OW1B 22528
#define OW2A 45056
#define OW2B 79872
#define OA0  114688
#define OA1  149504
#define OPAR 184320
#define OSTAT 186880
#define SM_TOTAL 188928

#define NTILE (BB * MDOWN / 4)   // 2048

__global__ __launch_bounds__(256)
void mlp_mma_kernel(
    const float* __restrict__ x, const float* __restrict__ pos,
    const float* __restrict__ W1, const float* __restrict__ b1,
    const float* __restrict__ g1, const float* __restrict__ be1,
    const float* __restrict__ W2, const float* __restrict__ b2,
    const float* __restrict__ g2, const float* __restrict__ be2,
    float* __restrict__ xd)
{
    extern __shared__ char smc[];
    uint32_t sbase = smem_u32(smc);
    float* sP = (float*)(smc + OPAR);        // g1 be1 b2 g2 be2
    float* sStat = (float*)(smc + OSTAT);

    int t = threadIdx.x;
    int lane = t & 31, w = t >> 5;
    int mw = w & 3, nh = w >> 2;
    int g = lane >> 2, tq = lane & 3;

    // ---- stage params ----
    if (t < 128) {
        sP[t]       = g1[t];
        sP[128 + t] = be1[t];
        sP[256 + t] = b2[t];
        sP[384 + t] = g2[t];
        sP[512 + t] = be2[t];
    }
    // ---- stage W1 (rows n=0..127, k=0..79; k==67 -> b1) ----
    {
        int r = t >> 1, h = t & 1;
        #pragma unroll
        for (int kk = 0; kk < 40; kk += 2) {
            int k = h * 40 + kk;
            float v0 = (k < 67) ? W1[k * COUT + r] : 0.0f;
            float v1 = (k + 1 < 67) ? W1[(k + 1) * COUT + r] : ((k + 1 == 67) ? b1[r] : 0.0f);
            uint32_t p0, p1;
            split2(v0, v1, p0, p1);
            *(uint32_t*)(smc + OW1A + r * STR1 + k * 2) = p0;
            *(uint32_t*)(smc + OW1B + r * STR1 + k * 2) = p1;
        }
    }
    // ---- stage W2 ----
    {
        int r = t >> 1, h = t & 1;
        #pragma unroll
        for (int kk = 0; kk < 64; kk += 2) {
            int k = h * 64 + kk;
            float v0 = W2[k * COUT + r];
            float v1 = W2[(k + 1) * COUT + r];
            uint32_t p0, p1;
            split2(v0, v1, p0, p1);
            *(uint32_t*)(smc + OW2A + r * STR2 + k * 2) = p0;
            *(uint32_t*)(smc + OW2B + r * STR2 + k * 2) = p1;
        }
    }

    // fragment base addresses (constant across tiles)
    int arow = mw * 32 + (lane & 15);
    int brow = nh * 64 + (lane & 7) + ((lane >> 4) << 3);
    int koff16 = ((lane >> 3) & 1) * 16;
    int acolg = (lane >> 4) * 16;

    uint32_t a1A = sbase + OA0 + arow * STR1 + acolg;
    uint32_t a1B = sbase + OA1 + arow * STR1 + acolg;
    uint32_t a2A = sbase + OA0 + arow * STR2 + acolg;
    uint32_t a2B = sbase + OA1 + arow * STR2 + acolg;
    uint32_t b1A[4], b1B[4], b2A[4], b2B[4];
    #pragma unroll
    for (int jj = 0; jj < 4; jj++) {
        b1A[jj] = sbase + OW1A + brow * STR1 + koff16 + jj * 16 * STR1;
        b1B[jj] = sbase + OW1B + brow * STR1 + koff16 + jj * 16 * STR1;
        b2A[jj] = sbase + OW2A + brow * STR2 + koff16 + jj * 16 * STR2;
        b2B[jj] = sbase + OW2B + brow * STR2 + koff16 + jj * 16 * STR2;
    }
    __syncthreads();

    for (int tile = blockIdx.x; tile < NTILE; tile += gridDim.x) {
        int g0 = tile * 4;

        // ---- gather A (layer1): row r = t>>1, half h = t&1 ----
        {
            int r = t >> 1, h = t & 1;
            int p = r >> 5;
            int gpt = g0 + p;
            int b = gpt >> 10;
            int ii = gpt & (MDOWN - 1);
            int idx = g_knn[tile * 128 + r];
            const float4* xr = (const float4*)(x + ((size_t)(b * NPER + idx)) * CIN) + h * 8;
            char* rowA = smc + OA0 + r * STR1 + h * 64;
            char* rowB = smc + OA1 + r * STR1 + h * 64;
            #pragma unroll
            for (int q = 0; q < 8; q++) {
                float4 f = xr[q];
                uint32_t p0, p1;
                split2(f.x, f.y, p0, p1);
                *(uint32_t*)(rowA + q * 8)     = p0;
                *(uint32_t*)(rowB + q * 8)     = p1;
                split2(f.z, f.w, p0, p1);
                *(uint32_t*)(rowA + q * 8 + 4) = p0;
                *(uint32_t*)(rowB + q * 8 + 4) = p1;
            }
            if (h) {
                const float* pn = pos + ((size_t)(b * NPER + idx)) * 3;
                const float* pc = pos + ((size_t)(b * NPER + ii)) * 3;
                char* rA = smc + OA0 + r * STR1;
                char* rB = smc + OA1 + r * STR1;
                uint32_t p0, p1;
                split2(pn[0] - pc[0], pn[1] - pc[1], p0, p1);
                *(uint32_t*)(rA + 128) = p0;
                *(uint32_t*)(rB + 128) = p1;
                split2(pn[2] - pc[2], 1.0f, p0, p1);   // col 67 = bias input
                *(uint32_t*)(rA + 132) = p0;
                *(uint32_t*)(rB + 132) = p1;
                #pragma unroll
                for (int kk = 136; kk < 160; kk += 4) {
                    *(uint32_t*)(rA + kk) = 0u;
                    *(uint32_t*)(rB + kk) = 0u;
                }
            }
        }
        __syncthreads();

        // ================= layer 1 GEMM (K=80) =================
        float d[2][8][4];
        #pragma unroll
        for (int i = 0; i < 2; i++)
            #pragma unroll
            for (int j = 0; j < 8; j++)
                #pragma unroll
                for (int q = 0; q < 4; q++) d[i][j][q] = 0.0f;
        gemm_tile<5>(a1A, a1A + 16 * STR1, b1A, d);
        gemm_tile<5>(a1B, a1B + 16 * STR1, b1A, d);
        gemm_tile<5>(a1A, a1A + 16 * STR1, b1B, d);

        // ---- epi1: fragment LN + GELU + split -> A (layer2 layout) ----
        float sv[2][2], qv[2][2], muv[2][2], invv[2][2];
        #pragma unroll
        for (int i = 0; i < 2; i++)
            #pragma unroll
            for (int sub = 0; sub < 2; sub++) {
                float s = 0.0f, q = 0.0f;
                #pragma unroll
                for (int j = 0; j < 8; j++) {
                    float u0 = d[i][j][2 * sub], u1 = d[i][j][2 * sub + 1];
                    s += u0 + u1;
                    q = fmaf(u0, u0, fmaf(u1, u1, q));
                }
                s += __shfl_xor_sync(0xffffffffu, s, 1);
                s += __shfl_xor_sync(0xffffffffu, s, 2);
                q += __shfl_xor_sync(0xffffffffu, q, 1);
                q += __shfl_xor_sync(0xffffffffu, q, 2);
                sv[i][sub] = s; qv[i][sub] = q;
                if (tq == 0) {
                    int row = mw * 32 + i * 16 + g + 8 * sub;
                    *(float2*)&sStat[(nh * 128 + row) * 2] = make_float2(s, q);
                }
            }
        __syncthreads();
        #pragma unroll
        for (int i = 0; i < 2; i++)
            #pragma unroll
            for (int sub = 0; sub < 2; sub++) {
                int row = mw * 32 + i * 16 + g + 8 * sub;
                float2 o = *(float2*)&sStat[((nh ^ 1) * 128 + row) * 2];
                float s = sv[i][sub] + o.x, q = qv[i][sub] + o.y;
                float mu = s * (1.0f / COUT);
                float var = q * (1.0f / COUT) - mu * mu;
                muv[i][sub] = mu;
                invv[i][sub] = rsqrtf(var + EPSV);
            }
        #pragma unroll
        for (int j = 0; j < 8; j++) {
            int c = nh * 64 + j * 8 + 2 * tq;
            float2 gg = *(float2*)&sP[c];
            float2 bb = *(float2*)&sP[128 + c];
            #pragma unroll
            for (int i = 0; i < 2; i++)
                #pragma unroll
                for (int sub = 0; sub < 2; sub++) {
                    float v0 = (d[i][j][2 * sub]     - muv[i][sub]) * invv[i][sub] * gg.x + bb.x;
                    float v1 = (d[i][j][2 * sub + 1] - muv[i][sub]) * invv[i][sub] * gg.y + bb.y;
                    v0 = gelu_exact(v0);
                    v1 = gelu_exact(v1);
                    uint32_t p0, p1;
                    split2(v0, v1, p0, p1);
                    int row = mw * 32 + i * 16 + g + 8 * sub;
                    uint32_t off = row * STR2 + c * 2;
                    *(uint32_t*)(smc + OA0 + off) = p0;
                    *(uint32_t*)(smc + OA1 + off) = p1;
                }
        }
        __syncthreads();

        // ================= layer 2 GEMM (K=128) =================
        #pragma unroll
        for (int i = 0; i < 2; i++)
            #pragma unroll
            for (int j = 0; j < 8; j++)
                #pragma unroll
                for (int q = 0; q < 4; q++) d[i][j][q] = 0.0f;
        gemm_tile<8>(a2A, a2A + 16 * STR2, b2A, d);
        gemm_tile<8>(a2B, a2B + 16 * STR2, b2A, d);
        gemm_tile<8>(a2A, a2A + 16 * STR2, b2B, d);

        // ---- epi2: +b2, fragment LN, minmax-pool, 2x gelu, store ----
        #pragma unroll
        for (int j = 0; j < 8; j++) {
            int c = nh * 64 + j * 8 + 2 * tq;
            float2 b2p = *(float2*)&sP[256 + c];
            #pragma unroll
            for (int i = 0; i < 2; i++)
                #pragma unroll
                for (int sub = 0; sub < 2; sub++) {
                    d[i][j][2 * sub]     += b2p.x;
                    d[i][j][2 * sub + 1] += b2p.y;
                }
        }
        #pragma unroll
        for (int i = 0; i < 2; i++)
            #pragma unroll
            for (int sub = 0; sub < 2; sub++) {
                float s = 0.0f, q = 0.0f;
                #pragma unroll
                for (int j = 0; j < 8; j++) {
                    float u0 = d[i][j][2 * sub], u1 = d[i][j][2 * sub + 1];
                    s += u0 + u1;
                    q = fmaf(u0, u0, fmaf(u1, u1, q));
                }
                s += __shfl_xor_sync(0xffffffffu, s, 1);
                s += __shfl_xor_sync(0xffffffffu, s, 2);
                q += __shfl_xor_sync(0xffffffffu, q, 1);
                q += __shfl_xor_sync(0xffffffffu, q, 2);
                sv[i][sub] = s; qv[i][sub] = q;
                if (tq == 0) {
                    int row = mw * 32 + i * 16 + g + 8 * sub;
                    *(float2*)&sStat[(nh * 128 + row) * 2] = make_float2(s, q);
                }
            }
        __syncthreads();
        #pragma unroll
        for (int i = 0; i < 2; i++)
            #pragma unroll
            for (int sub = 0; sub < 2; sub++) {
                int row = mw * 32 + i * 16 + g + 8 * sub;
                float2 o = *(float2*)&sStat[((nh ^ 1) * 128 + row) * 2];
                float s = sv[i][sub] + o.x, q = qv[i][sub] + o.y;
                float mu = s * (1.0f / COUT);
                float var = q * (1.0f / COUT) - mu * mu;
                muv[i][sub] = mu;
                invv[i][sub] = rsqrtf(var + EPSV);
            }

        float mn0[8], mx0[8], mn1[8], mx1[8];
        #pragma unroll
        for (int j = 0; j < 8; j++) {
            int c = nh * 64 + j * 8 + 2 * tq;
            float2 g2p  = *(float2*)&sP[384 + c];
            float2 be2p = *(float2*)&sP[512 + c];
            float a0 = INFF, a1 = -INFF, a2 = INFF, a3 = -INFF;
            #pragma unroll
            for (int i = 0; i < 2; i++)
                #pragma unroll
                for (int sub = 0; sub < 2; sub++) {
                    float v0 = (d[i][j][2 * sub]     - muv[i][sub]) * invv[i][sub] * g2p.x + be2p.x;
                    float v1 = (d[i][j][2 * sub + 1] - muv[i][sub]) * invv[i][sub] * g2p.y + be2p.y;
                    a0 = fminf(a0, v0); a1 = fmaxf(a1, v0);
                    a2 = fminf(a2, v1); a3 = fmaxf(a3, v1);
                }
            mn0[j] = a0; mx0[j] = a1; mn1[j] = a2; mx1[j] = a3;
        }
        #pragma unroll
        for (int o = 4; o <= 16; o <<= 1) {
            #pragma unroll
            for (int j = 0; j < 8; j++) {
                mn0[j] = fminf(mn0[j], __shfl_xor_sync(0xffffffffu, mn0[j], o));
                mx0[j] = fmaxf(mx0[j], __shfl_xor_sync(0xffffffffu, mx0[j], o));
                mn1[j] = fminf(mn1[j], __shfl_xor_sync(0xffffffffu, mn1[j], o));
                mx1[j] = fmaxf(mx1[j], __shfl_xor_sync(0xffffffffu, mx1[j], o));
            }
        }
        if (g == 0) {
            #pragma unroll
            for (int j = 0; j < 8; j++) {
                float o0 = fmaxf(gelu_exact(mn0[j]), gelu_exact(mx0[j]));
                float o1 = fmaxf(gelu_exact(mn1[j]), gelu_exact(mx1[j]));
                int c = nh * 64 + j * 8 + 2 * tq;
                *(float2*)&xd[(size_t)(g0 + mw) * COUT + c] = make_float2(o0, o1);
            }
        }
        __syncthreads();
    }
}

// ---------------------------------------------------------------------------
// Kernel 3: upsample nearest index (unchanged)
// ---------------------------------------------------------------------------
__global__ __launch_bounds__(256) void upsample_kernel(
    const float* __restrict__ pos, float* __restrict__ outF,
    long long* __restrict__ outI, int mode)
{
    __shared__ float pd[MDOWN * 3];
    int b = blockIdx.y;
    const float* pbase = pos + (size_t)b * NPER * 3;
    for (int u = threadIdx.x; u < MDOWN * 3; u += 256) pd[u] = pbase[u];
    __syncthreads();

    int p = blockIdx.x * 256 + threadIdx.x;
    float qx = pbase[p * 3 + 0];
    float qy = pbase[p * 3 + 1];
    float qz = pbase[p * 3 + 2];
    float bd = INFF; int bi = 0;
    for (int j = 0; j < MDOWN; j++) {
        float dx = qx - pd[j * 3 + 0];
        float dy = qy - pd[j * 3 + 1];
        float dz = qz - pd[j * 3 + 2];
        float d = dx * dx + dy * dy + dz * dz;
        if (d < bd) { bd = d; bi = j; }
    }
    long long res = (long long)bi + (long long)b * MDOWN;
    int gidx = b * NPER + p;
    if (mode) outI[gidx] = res;
    else      outF[gidx] = (float)res;
}

// ---------------------------------------------------------------------------
// Kernel 4: pos_down / batch_down (unchanged)
// ---------------------------------------------------------------------------
__global__ __launch_bounds__(256) void misc_kernel(
    const float* __restrict__ pos, float* __restrict__ outBase, int mode)
{
    int t = blockIdx.x * 256 + threadIdx.x;
    if (t >= BB * MDOWN) return;
    int b = t >> 10;
    int i = t & (MDOWN - 1);
    const float* src = pos + ((size_t)b * NPER + i) * 3;
    float* pdst = outBase + (size_t)BB * MDOWN * COUT + (size_t)t * 3;
    pdst[0] = src[0]; pdst[1] = src[1]; pdst[2] = src[2];
    if (mode) {
        long long* bd = (long long*)((char*)outBase
            + (size_t)(BB * MDOWN * COUT + BB * MDOWN * 3) * 4);
        bd[t] = (long long)b;
    } else {
        outBase[(size_t)BB * MDOWN * COUT + BB * MDOWN * 3 + t] = (float)b;
    }
}

// ---------------------------------------------------------------------------
// launcher
// ---------------------------------------------------------------------------
extern "C" void kernel_launch(void* const* d_in, const int* in_sizes, int n_in,
                              void* d_out, int out_size)
{
    const float* x   = (const float*)d_in[0];
    const float* pos = (const float*)d_in[1];
    const float* W1  = (const float*)d_in[3];
    const float* b1  = (const float*)d_in[4];
    const float* g1  = (const float*)d_in[5];
    const float* be1 = (const float*)d_in[6];
    const float* W2  = (const float*)d_in[7];
    const float* b2  = (const float*)d_in[8];
    const float* g2  = (const float*)d_in[9];
    const float* be2 = (const float*)d_in[10];
    float* out = (float*)d_out;

    const int FLOAT_FULL = BB * MDOWN * COUT + BB * MDOWN * 3 + BB * MDOWN + BB * NPER;
    const int I64_FULL   = BB * MDOWN * COUT + BB * MDOWN * 3 + 2 * (BB * MDOWN + BB * NPER);
    int mode;
    if (out_size == I64_FULL)        mode = 1;
    else if (out_size >= FLOAT_FULL) mode = 0;
    else                             mode = 2;

    static int smem_set = 0;
    if (!smem_set) {
        cudaFuncSetAttribute(mlp_mma_kernel,
            cudaFuncAttributeMaxDynamicSharedMemorySize, SM_TOTAL);
        smem_set = 1;
    }

    knn_kernel<<<BB * MDOWN, 128>>>(pos);

    mlp_mma_kernel<<<152, 256, SM_TOTAL>>>(
        x, pos, W1, b1, g1, be1, W2, b2, g2, be2, out);

    if (mode != 2) {
        long long* outUI = (long long*)((char*)d_out
            + (size_t)(BB * MDOWN * COUT + BB * MDOWN * 3) * 4
            + (size_t)(BB * MDOWN) * 8);
        float* outUF = out + (size_t)(BB * MDOWN * COUT + BB * MDOWN * 3 + BB * MDOWN);
        dim3 ug(NPER / 256, BB);
        upsample_kernel<<<ug, 256>>>(pos, outUF, outUI, mode);
        misc_kernel<<<(BB * MDOWN + 255) / 256, 256>>>(pos, out, mode);
    }
}

// round 5
// speedup vs baseline: 2.9160x; 1.1451x over previous
#include <cuda_runtime.h>
#include <cuda_bf16.h>
#include <cstdint>
#include <cstddef>

#define BB    8
#define NPER  4096
#define MDOWN 1024
#define KNN   32
#define CIN   64
#define COUT  128
#define EPSV  1e-5f

#define INFF __int_as_float(0x7f800000)

__device__ int g_knn[BB * MDOWN * KNN];

// ---------------------------------------------------------------------------
// helpers
// ---------------------------------------------------------------------------
__device__ __forceinline__ uint32_t smem_u32(const void* p) {
    uint32_t a;
    asm("{ .reg .u64 t; cvta.to.shared.u64 t, %1; cvt.u32.u64 %0, t; }" : "=r"(a) : "l"(p));
    return a;
}

__device__ __forceinline__ void ldsm4(uint32_t* r, uint32_t addr) {
    asm volatile("ldmatrix.sync.aligned.m8n8.x4.shared.b16 {%0,%1,%2,%3}, [%4];"
        : "=r"(r[0]), "=r"(r[1]), "=r"(r[2]), "=r"(r[3]) : "r"(addr));
}

__device__ __forceinline__ void mma16816(float* d, const uint32_t* a, const uint32_t* b) {
    asm volatile(
        "mma.sync.aligned.m16n8k16.row.col.f32.bf16.bf16.f32 "
        "{%0,%1,%2,%3}, {%4,%5,%6,%7}, {%8,%9}, {%0,%1,%2,%3};"
        : "+f"(d[0]), "+f"(d[1]), "+f"(d[2]), "+f"(d[3])
        : "r"(a[0]), "r"(a[1]), "r"(a[2]), "r"(a[3]), "r"(b[0]), "r"(b[1]));
}

__device__ __forceinline__ void split2(float v0, float v1, uint32_t& p0, uint32_t& p1) {
    __nv_bfloat162 h0 = __floats2bfloat162_rn(v0, v1);
    uint32_t u = *reinterpret_cast<uint32_t*>(&h0);
    float f0 = __uint_as_float(u << 16);
    float f1 = __uint_as_float(u & 0xffff0000u);
    __nv_bfloat162 h1 = __floats2bfloat162_rn(v0 - f0, v1 - f1);
    p0 = u;
    p1 = *reinterpret_cast<uint32_t*>(&h1);
}

__device__ __forceinline__ float gelu_exact(float v) {
    return 0.5f * v * (1.0f + erff(v * 0.7071067811865476f));
}

template<int NK>
__device__ __forceinline__ void gemm_tile(uint32_t a0Addr, uint32_t a1Addr,
                                          const uint32_t* bAddr, float (*d)[8][4]) {
    #pragma unroll
    for (int k = 0; k < NK; k++) {
        uint32_t a0[4], a1[4];
        ldsm4(a0, a0Addr + k * 32);
        ldsm4(a1, a1Addr + k * 32);
        #pragma unroll
        for (int jj = 0; jj < 4; jj++) {
            uint32_t bb[4];
            ldsm4(bb, bAddr[jj] + k * 32);
            mma16816(d[0][2 * jj],     a0, bb);
            mma16816(d[0][2 * jj + 1], a0, bb + 2);
            mma16816(d[1][2 * jj],     a1, bb);
            mma16816(d[1][2 * jj + 1], a1, bb + 2);
        }
    }
}

// ---------------------------------------------------------------------------
// Kernel 1: kNN via register bisection-select + warp bitonic. 1 block = 1 query.
// ---------------------------------------------------------------------------
__device__ __forceinline__ unsigned long long blk_red64(
    unsigned long long v, int lane, int warp, unsigned long long* wr)
{
    #pragma unroll
    for (int o = 16; o; o >>= 1) v += __shfl_xor_sync(0xffffffffu, v, o);
    __syncthreads();                      // protect prior reads of wr
    if (lane == 0) wr[warp] = v;
    __syncthreads();
    return wr[0] + wr[1] + wr[2] + wr[3];
}

__device__ __forceinline__ unsigned long long bitonic_ce(
    unsigned long long v, int e, int j, int k)
{
    unsigned long long p = __shfl_xor_sync(0xffffffffu, v, j);
    bool up  = ((e & k) == 0);
    bool low = ((e & j) == 0);
    unsigned long long mn = (v < p) ? v : p;
    unsigned long long mx = (v < p) ? p : v;
    return (up == low) ? mn : mx;
}

__global__ __launch_bounds__(128) void knn_kernel(const float* __restrict__ pos)
{
    __shared__ unsigned long long wred[4];
    __shared__ unsigned long long cand[64];
    __shared__ int scnt;

    int blk = blockIdx.x;
    int b = blk >> 10;
    int i = blk & (MDOWN - 1);
    int t = threadIdx.x;
    int lane = t & 31, warp = t >> 5;
    const float* pbase = pos + (size_t)b * NPER * 3;

    float qx = pbase[i * 3 + 0];
    float qy = pbase[i * 3 + 1];
    float qz = pbase[i * 3 + 2];

    // distances in registers (float bits; d2 >= 0 so uint order == float order)
    uint32_t vb[32];
    #pragma unroll
    for (int s = 0; s < 32; s++) {
        int p = t + s * 128;
        float dx = pbase[p * 3 + 0] - qx;
        float dy = pbase[p * 3 + 1] - qy;
        float dz = pbase[p * 3 + 2] - qz;
        vb[s] = __float_as_uint(dx * dx + dy * dy + dz * dz);
    }

    // bracket pass: 3 thresholds counted at once (packed u64 reduce)
    const uint32_t T1 = 0x3C23D70Au;  // 0.01
    const uint32_t T2 = 0x3D75C28Fu;  // 0.06
    const uint32_t T3 = 0x3E800000u;  // 0.25
    {
        unsigned int c1 = 0, c2 = 0, c3 = 0;
        #pragma unroll
        for (int s = 0; s < 32; s++) {
            c1 += (vb[s] < T1);
            c2 += (vb[s] < T2);
            c3 += (vb[s] < T3);
        }
        unsigned long long packed =
            (unsigned long long)c1 | ((unsigned long long)c2 << 16) |
            ((unsigned long long)c3 << 32);
        unsigned long long tot = blk_red64(packed, lane, warp, wred);
        unsigned int C1 = (unsigned int)(tot & 0xffff);
        unsigned int C2 = (unsigned int)((tot >> 16) & 0xffff);
        unsigned int C3 = (unsigned int)((tot >> 32) & 0xffff);

        uint32_t lo, hi;
        unsigned int chi;
        if (C1 >= KNN)      { lo = 0;  hi = T1; chi = C1; }
        else if (C2 >= KNN) { lo = T1; hi = T2; chi = C2; }
        else if (C3 >= KNN) { lo = T2; hi = T3; chi = C3; }
        else                { lo = T3; hi = 0x7f800000u; chi = NPER; }

        // bisection on float bits until candidate set fits in 64
        for (int it = 0; it < 24 && chi > 64 && (hi - lo) > 1; it++) {
            uint32_t mid = (lo + hi) >> 1;
            unsigned int c = 0;
            #pragma unroll
            for (int s = 0; s < 32; s++) c += (vb[s] < mid);
            unsigned long long ct = blk_red64(c, lane, warp, wred);
            if ((unsigned int)ct >= KNN) { hi = mid; chi = (unsigned int)ct; }
            else                         lo = mid;
        }

        // gather candidates < hi
        if (t == 0) scnt = 0;
        __syncthreads();
        #pragma unroll
        for (int s = 0; s < 32; s++) {
            if (vb[s] < hi) {
                int slot = atomicAdd(&scnt, 1);
                if (slot < 64)
                    cand[slot] = ((unsigned long long)vb[s] << 32) |
                                 (unsigned)(t + s * 128);
            }
        }
        __syncthreads();
        int n = scnt; if (n > 64) n = 64;
        if (t < 64 && t >= n) cand[t] = ~0ull;
        __syncthreads();
    }

    // warp 0: bitonic sort of 64 keys (2 per lane), ascending
    if (warp == 0) {
        unsigned long long r0 = cand[lane];
        unsigned long long r1 = cand[lane + 32];
        #pragma unroll
        for (int k = 2; k <= 64; k <<= 1) {
            if (k == 64) {
                unsigned long long mn = (r0 < r1) ? r0 : r1;
                unsigned long long mx = (r0 < r1) ? r1 : r0;
                r0 = mn; r1 = mx;
            }
            int jstart = (k == 64) ? 16 : (k >> 1);
            for (int j = jstart; j > 0; j >>= 1) {
                r0 = bitonic_ce(r0, lane, j, k);
                r1 = bitonic_ce(r1, lane + 32, j, k);
            }
        }
        // elements 0..31 (ascending) live in r0 across lanes
        g_knn[blk * KNN + lane] = (int)(r0 & 0xffffffffu);
    }
}

// ---------------------------------------------------------------------------
// Kernel 2: persistent HMMA MLP (unchanged from passing round 4)
// ---------------------------------------------------------------------------
#define STR1 176
#define STR2 272

#define OW1A 0
#define OW1B 22528
#define OW2A 45056
#define OW2B 79872
#define OA0  114688
#define OA1  149504
#define OPAR 184320
#define OSTAT 186880
#define SM_TOTAL 188928

#define NTILE (BB * MDOWN / 4)   // 2048

__global__ __launch_bounds__(256)
void mlp_mma_kernel(
    const float* __restrict__ x, const float* __restrict__ pos,
    const float* __restrict__ W1, const float* __restrict__ b1,
    const float* __restrict__ g1, const float* __restrict__ be1,
    const float* __restrict__ W2, const float* __restrict__ b2,
    const float* __restrict__ g2, const float* __restrict__ be2,
    float* __restrict__ xd)
{
    extern __shared__ char smc[];
    uint32_t sbase = smem_u32(smc);
    float* sP = (float*)(smc + OPAR);
    float* sStat = (float*)(smc + OSTAT);

    int t = threadIdx.x;
    int lane = t & 31, w = t >> 5;
    int mw = w & 3, nh = w >> 2;
    int g = lane >> 2, tq = lane & 3;

    if (t < 128) {
        sP[t]       = g1[t];
        sP[128 + t] = be1[t];
        sP[256 + t] = b2[t];
        sP[384 + t] = g2[t];
        sP[512 + t] = be2[t];
    }
    {
        int r = t >> 1, h = t & 1;
        #pragma unroll
        for (int kk = 0; kk < 40; kk += 2) {
            int k = h * 40 + kk;
            float v0 = (k < 67) ? W1[k * COUT + r] : 0.0f;
            float v1 = (k + 1 < 67) ? W1[(k + 1) * COUT + r] : ((k + 1 == 67) ? b1[r] : 0.0f);
            uint32_t p0, p1;
            split2(v0, v1, p0, p1);
            *(uint32_t*)(smc + OW1A + r * STR1 + k * 2) = p0;
            *(uint32_t*)(smc + OW1B + r * STR1 + k * 2) = p1;
        }
    }
    {
        int r = t >> 1, h = t & 1;
        #pragma unroll
        for (int kk = 0; kk < 64; kk += 2) {
            int k = h * 64 + kk;
            float v0 = W2[k * COUT + r];
            float v1 = W2[(k + 1) * COUT + r];
            uint32_t p0, p1;
            split2(v0, v1, p0, p1);
            *(uint32_t*)(smc + OW2A + r * STR2 + k * 2) = p0;
            *(uint32_t*)(smc + OW2B + r * STR2 + k * 2) = p1;
        }
    }

    int arow = mw * 32 + (lane & 15);
    int brow = nh * 64 + (lane & 7) + ((lane >> 4) << 3);
    int koff16 = ((lane >> 3) & 1) * 16;
    int acolg = (lane >> 4) * 16;

    uint32_t a1A = sbase + OA0 + arow * STR1 + acolg;
    uint32_t a1B = sbase + OA1 + arow * STR1 + acolg;
    uint32_t a2A = sbase + OA0 + arow * STR2 + acolg;
    uint32_t a2B = sbase + OA1 + arow * STR2 + acolg;
    uint32_t b1A[4], b1B[4], b2A[4], b2B[4];
    #pragma unroll
    for (int jj = 0; jj < 4; jj++) {
        b1A[jj] = sbase + OW1A + brow * STR1 + koff16 + jj * 16 * STR1;
        b1B[jj] = sbase + OW1B + brow * STR1 + koff16 + jj * 16 * STR1;
        b2A[jj] = sbase + OW2A + brow * STR2 + koff16 + jj * 16 * STR2;
        b2B[jj] = sbase + OW2B + brow * STR2 + koff16 + jj * 16 * STR2;
    }
    __syncthreads();

    for (int tile = blockIdx.x; tile < NTILE; tile += gridDim.x) {
        int g0 = tile * 4;

        {
            int r = t >> 1, h = t & 1;
            int p = r >> 5;
            int gpt = g0 + p;
            int b = gpt >> 10;
            int ii = gpt & (MDOWN - 1);
            int idx = g_knn[tile * 128 + r];
            const float4* xr = (const float4*)(x + ((size_t)(b * NPER + idx)) * CIN) + h * 8;
            char* rowA = smc + OA0 + r * STR1 + h * 64;
            char* rowB = smc + OA1 + r * STR1 + h * 64;
            #pragma unroll
            for (int q = 0; q < 8; q++) {
                float4 f = xr[q];
                uint32_t p0, p1;
                split2(f.x, f.y, p0, p1);
                *(uint32_t*)(rowA + q * 8)     = p0;
                *(uint32_t*)(rowB + q * 8)     = p1;
                split2(f.z, f.w, p0, p1);
                *(uint32_t*)(rowA + q * 8 + 4) = p0;
                *(uint32_t*)(rowB + q * 8 + 4) = p1;
            }
            if (h) {
                const float* pn = pos + ((size_t)(b * NPER + idx)) * 3;
                const float* pc = pos + ((size_t)(b * NPER + ii)) * 3;
                char* rA = smc + OA0 + r * STR1;
                char* rB = smc + OA1 + r * STR1;
                uint32_t p0, p1;
                split2(pn[0] - pc[0], pn[1] - pc[1], p0, p1);
                *(uint32_t*)(rA + 128) = p0;
                *(uint32_t*)(rB + 128) = p1;
                split2(pn[2] - pc[2], 1.0f, p0, p1);
                *(uint32_t*)(rA + 132) = p0;
                *(uint32_t*)(rB + 132) = p1;
                #pragma unroll
                for (int kk = 136; kk < 160; kk += 4) {
                    *(uint32_t*)(rA + kk) = 0u;
                    *(uint32_t*)(rB + kk) = 0u;
                }
            }
        }
        __syncthreads();

        float d[2][8][4];
        #pragma unroll
        for (int i = 0; i < 2; i++)
            #pragma unroll
            for (int j = 0; j < 8; j++)
                #pragma unroll
                for (int q = 0; q < 4; q++) d[i][j][q] = 0.0f;
        gemm_tile<5>(a1A, a1A + 16 * STR1, b1A, d);
        gemm_tile<5>(a1B, a1B + 16 * STR1, b1A, d);
        gemm_tile<5>(a1A, a1A + 16 * STR1, b1B, d);

        float sv[2][2], qv[2][2], muv[2][2], invv[2][2];
        #pragma unroll
        for (int i = 0; i < 2; i++)
            #pragma unroll
            for (int sub = 0; sub < 2; sub++) {
                float s = 0.0f, q = 0.0f;
                #pragma unroll
                for (int j = 0; j < 8; j++) {
                    float u0 = d[i][j][2 * sub], u1 = d[i][j][2 * sub + 1];
                    s += u0 + u1;
                    q = fmaf(u0, u0, fmaf(u1, u1, q));
                }
                s += __shfl_xor_sync(0xffffffffu, s, 1);
                s += __shfl_xor_sync(0xffffffffu, s, 2);
                q += __shfl_xor_sync(0xffffffffu, q, 1);
                q += __shfl_xor_sync(0xffffffffu, q, 2);
                sv[i][sub] = s; qv[i][sub] = q;
                if (tq == 0) {
                    int row = mw * 32 + i * 16 + g + 8 * sub;
                    *(float2*)&sStat[(nh * 128 + row) * 2] = make_float2(s, q);
                }
            }
        __syncthreads();
        #pragma unroll
        for (int i = 0; i < 2; i++)
            #pragma unroll
            for (int sub = 0; sub < 2; sub++) {
                int row = mw * 32 + i * 16 + g + 8 * sub;
                float2 o = *(float2*)&sStat[((nh ^ 1) * 128 + row) * 2];
                float s = sv[i][sub] + o.x, q = qv[i][sub] + o.y;
                float mu = s * (1.0f / COUT);
                float var = q * (1.0f / COUT) - mu * mu;
                muv[i][sub] = mu;
                invv[i][sub] = rsqrtf(var + EPSV);
            }
        #pragma unroll
        for (int j = 0; j < 8; j++) {
            int c = nh * 64 + j * 8 + 2 * tq;
            float2 gg = *(float2*)&sP[c];
            float2 bb = *(float2*)&sP[128 + c];
            #pragma unroll
            for (int i = 0; i < 2; i++)
                #pragma unroll
                for (int sub = 0; sub < 2; sub++) {
                    float v0 = (d[i][j][2 * sub]     - muv[i][sub]) * invv[i][sub] * gg.x + bb.x;
                    float v1 = (d[i][j][2 * sub + 1] - muv[i][sub]) * invv[i][sub] * gg.y + bb.y;
                    v0 = gelu_exact(v0);
                    v1 = gelu_exact(v1);
                    uint32_t p0, p1;
                    split2(v0, v1, p0, p1);
                    int row = mw * 32 + i * 16 + g + 8 * sub;
                    uint32_t off = row * STR2 + c * 2;
                    *(uint32_t*)(smc + OA0 + off) = p0;
                    *(uint32_t*)(smc + OA1 + off) = p1;
                }
        }
        __syncthreads();

        #pragma unroll
        for (int i = 0; i < 2; i++)
            #pragma unroll
            for (int j = 0; j < 8; j++)
                #pragma unroll
                for (int q = 0; q < 4; q++) d[i][j][q] = 0.0f;
        gemm_tile<8>(a2A, a2A + 16 * STR2, b2A, d);
        gemm_tile<8>(a2B, a2B + 16 * STR2, b2A, d);
        gemm_tile<8>(a2A, a2A + 16 * STR2, b2B, d);

        #pragma unroll
        for (int j = 0; j < 8; j++) {
            int c = nh * 64 + j * 8 + 2 * tq;
            float2 b2p = *(float2*)&sP[256 + c];
            #pragma unroll
            for (int i = 0; i < 2; i++)
                #pragma unroll
                for (int sub = 0; sub < 2; sub++) {
                    d[i][j][2 * sub]     += b2p.x;
                    d[i][j][2 * sub + 1] += b2p.y;
                }
        }
        #pragma unroll
        for (int i = 0; i < 2; i++)
            #pragma unroll
            for (int sub = 0; sub < 2; sub++) {
                float s = 0.0f, q = 0.0f;
                #pragma unroll
                for (int j = 0; j < 8; j++) {
                    float u0 = d[i][j][2 * sub], u1 = d[i][j][2 * sub + 1];
                    s += u0 + u1;
                    q = fmaf(u0, u0, fmaf(u1, u1, q));
                }
                s += __shfl_xor_sync(0xffffffffu, s, 1);
                s += __shfl_xor_sync(0xffffffffu, s, 2);
                q += __shfl_xor_sync(0xffffffffu, q, 1);
                q += __shfl_xor_sync(0xffffffffu, q, 2);
                sv[i][sub] = s; qv[i][sub] = q;
                if (tq == 0) {
                    int row = mw * 32 + i * 16 + g + 8 * sub;
                    *(float2*)&sStat[(nh * 128 + row) * 2] = make_float2(s, q);
                }
            }
        __syncthreads();
        #pragma unroll
        for (int i = 0; i < 2; i++)
            #pragma unroll
            for (int sub = 0; sub < 2; sub++) {
                int row = mw * 32 + i * 16 + g + 8 * sub;
                float2 o = *(float2*)&sStat[((nh ^ 1) * 128 + row) * 2];
                float s = sv[i][sub] + o.x, q = qv[i][sub] + o.y;
                float mu = s * (1.0f / COUT);
                float var = q * (1.0f / COUT) - mu * mu;
                muv[i][sub] = mu;
                invv[i][sub] = rsqrtf(var + EPSV);
            }

        float mn0[8], mx0[8], mn1[8], mx1[8];
        #pragma unroll
        for (int j = 0; j < 8; j++) {
            int c = nh * 64 + j * 8 + 2 * tq;
            float2 g2p  = *(float2*)&sP[384 + c];
            float2 be2p = *(float2*)&sP[512 + c];
            float a0 = INFF, a1 = -INFF, a2 = INFF, a3 = -INFF;
            #pragma unroll
            for (int i = 0; i < 2; i++)
                #pragma unroll
                for (int sub = 0; sub < 2; sub++) {
                    float v0 = (d[i][j][2 * sub]     - muv[i][sub]) * invv[i][sub] * g2p.x + be2p.x;
                    float v1 = (d[i][j][2 * sub + 1] - muv[i][sub]) * invv[i][sub] * g2p.y + be2p.y;
                    a0 = fminf(a0, v0); a1 = fmaxf(a1, v0);
                    a2 = fminf(a2, v1); a3 = fmaxf(a3, v1);
                }
            mn0[j] = a0; mx0[j] = a1; mn1[j] = a2; mx1[j] = a3;
        }
        #pragma unroll
        for (int o = 4; o <= 16; o <<= 1) {
            #pragma unroll
            for (int j = 0; j < 8; j++) {
                mn0[j] = fminf(mn0[j], __shfl_xor_sync(0xffffffffu, mn0[j], o));
                mx0[j] = fmaxf(mx0[j], __shfl_xor_sync(0xffffffffu, mx0[j], o));
                mn1[j] = fminf(mn1[j], __shfl_xor_sync(0xffffffffu, mn1[j], o));
                mx1[j] = fmaxf(mx1[j], __shfl_xor_sync(0xffffffffu, mx1[j], o));
            }
        }
        if (g == 0) {
            #pragma unroll
            for (int j = 0; j < 8; j++) {
                float o0 = fmaxf(gelu_exact(mn0[j]), gelu_exact(mx0[j]));
                float o1 = fmaxf(gelu_exact(mn1[j]), gelu_exact(mx1[j]));
                int c = nh * 64 + j * 8 + 2 * tq;
                *(float2*)&xd[(size_t)(g0 + mw) * COUT + c] = make_float2(o0, o1);
            }
        }
        __syncthreads();
    }
}

// ---------------------------------------------------------------------------
// Kernel 3: upsample nearest index — 4 threads per query, shfl reduce.
// ---------------------------------------------------------------------------
__global__ __launch_bounds__(256) void upsample_kernel(
    const float* __restrict__ pos, float* __restrict__ outF,
    long long* __restrict__ outI, int mode)
{
    __shared__ float pd[MDOWN * 3];
    int b = blockIdx.y;
    const float* pbase = pos + (size_t)b * NPER * 3;
    for (int u = threadIdx.x; u < MDOWN * 3; u += 256) pd[u] = pbase[u];
    __syncthreads();

    int t = threadIdx.x;
    int q = blockIdx.x * 64 + (t >> 2);     // 0..4095
    int part = t & 3;
    float qx = pbase[q * 3 + 0];
    float qy = pbase[q * 3 + 1];
    float qz = pbase[q * 3 + 2];
    float bd = INFF; int bj = 0;
    #pragma unroll 4
    for (int jj = 0; jj < MDOWN / 4; jj++) {
        int j = 4 * jj + part;              // interleaved -> conflict-free LDS
        float dx = qx - pd[j * 3 + 0];
        float dy = qy - pd[j * 3 + 1];
        float dz = qz - pd[j * 3 + 2];
        float d = dx * dx + dy * dy + dz * dz;
        if (d < bd) { bd = d; bj = j; }
    }
    unsigned long long key =
        ((unsigned long long)__float_as_uint(bd) << 32) | (unsigned)bj;
    {
        unsigned long long o = __shfl_xor_sync(0xffffffffu, key, 1);
        if (o < key) key = o;
        o = __shfl_xor_sync(0xffffffffu, key, 2);
        if (o < key) key = o;
    }
    if (part == 0) {
        long long res = (long long)(unsigned)(key & 0xffffffffu) + (long long)b * MDOWN;
        int gidx = b * NPER + q;
        if (mode) outI[gidx] = res;
        else      outF[gidx] = (float)res;
    }
}

// ---------------------------------------------------------------------------
// Kernel 4: pos_down / batch_down (unchanged)
// ---------------------------------------------------------------------------
__global__ __launch_bounds__(256) void misc_kernel(
    const float* __restrict__ pos, float* __restrict__ outBase, int mode)
{
    int t = blockIdx.x * 256 + threadIdx.x;
    if (t >= BB * MDOWN) return;
    int b = t >> 10;
    int i = t & (MDOWN - 1);
    const float* src = pos + ((size_t)b * NPER + i) * 3;
    float* pdst = outBase + (size_t)BB * MDOWN * COUT + (size_t)t * 3;
    pdst[0] = src[0]; pdst[1] = src[1]; pdst[2] = src[2];
    if (mode) {
        long long* bd = (long long*)((char*)outBase
            + (size_t)(BB * MDOWN * COUT + BB * MDOWN * 3) * 4);
        bd[t] = (long long)b;
    } else {
        outBase[(size_t)BB * MDOWN * COUT + BB * MDOWN * 3 + t] = (float)b;
    }
}

// ---------------------------------------------------------------------------
// launcher
// ---------------------------------------------------------------------------
extern "C" void kernel_launch(void* const* d_in, const int* in_sizes, int n_in,
                              void* d_out, int out_size)
{
    const float* x   = (const float*)d_in[0];
    const float* pos = (const float*)d_in[1];
    const float* W1  = (const float*)d_in[3];
    const float* b1  = (const float*)d_in[4];
    const float* g1  = (const float*)d_in[5];
    const float* be1 = (const float*)d_in[6];
    const float* W2  = (const float*)d_in[7];
    const float* b2  = (const float*)d_in[8];
    const float* g2  = (const float*)d_in[9];
    const float* be2 = (const float*)d_in[10];
    float* out = (float*)d_out;

    const int FLOAT_FULL = BB * MDOWN * COUT + BB * MDOWN * 3 + BB * MDOWN + BB * NPER;
    const int I64_FULL   = BB * MDOWN * COUT + BB * MDOWN * 3 + 2 * (BB * MDOWN + BB * NPER);
    int mode;
    if (out_size == I64_FULL)        mode = 1;
    else if (out_size >= FLOAT_FULL) mode = 0;
    else                             mode = 2;

    static int smem_set = 0;
    if (!smem_set) {
        cudaFuncSetAttribute(mlp_mma_kernel,
            cudaFuncAttributeMaxDynamicSharedMemorySize, SM_TOTAL);
        smem_set = 1;
    }

    knn_kernel<<<BB * MDOWN, 128>>>(pos);

    mlp_mma_kernel<<<152, 256, SM_TOTAL>>>(
        x, pos, W1, b1, g1, be1, W2, b2, g2, be2, out);

    if (mode != 2) {
        long long* outUI = (long long*)((char*)d_out
            + (size_t)(BB * MDOWN * COUT + BB * MDOWN * 3) * 4
            + (size_t)(BB * MDOWN) * 8);
        float* outUF = out + (size_t)(BB * MDOWN * COUT + BB * MDOWN * 3 + BB * MDOWN);
        dim3 ug(NPER / 64, BB);
        upsample_kernel<<<ug, 256>>>(pos, outUF, outUI, mode);
        misc_kernel<<<(BB * MDOWN + 255) / 256, 256>>>(pos, out, mode);
    }
}